// round 11
// baseline (speedup 1.0000x reference)
#include <cuda_runtime.h>
#include <cuda_fp16.h>
#include <math.h>

#define NB 8192
#define NSLICE 37              // 4 x-blocks * 37 slices = 148 blocks = 1 block/SM
#define PSTRIDE 38             // padded partial stride; pad slot stays 0
#define RPT 4                  // rows per thread in attention
#define RSTRIDE (NB / RPT)     // 2048
#define NPAIR (RPT / 2)        // 2 packed row-pairs
#define JMAX 222               // max j per slice
#define NPREPB 256             // prep blocks (32 rows each)
#define LOG2E 1.4426950408889634f

typedef unsigned int u32;

// ---- scratch (device globals; no allocation allowed) ----
__device__ float4 gQ4[NB];                 // q * (0.5*log2e) per row (fp32)
__device__ float  gQn[NB];                 // |q_tilde| per row
__device__ uint4  gKh[NB];                 // {h2(kx,kx), h2(ky,ky), h2(kz,kz), h2(kw,kw)}
__device__ u32    gCh[NB];                 // h2(c,c), c = x . conv_w
__device__ __align__(16) float gKmaxBlk[NPREPB];  // per-prep-block max |k|
__device__ float4 gP[NB * PSTRIDE / 2];    // {sum,y} float2 pairs, padded

__device__ __forceinline__ __half2 u2h(u32 v) { __half2 h; *reinterpret_cast<u32*>(&h) = v; return h; }
__device__ __forceinline__ u32 h2u(__half2 h) { return *reinterpret_cast<u32*>(&h); }
__device__ __forceinline__ __half2 hexp2_x(__half2 v) {
    u32 r, s = h2u(v);
    asm("ex2.approx.f16x2 %0, %1;" : "=r"(r) : "r"(s));
    return u2h(r);
}
__device__ __forceinline__ float tanh_hw(float x) {
    float y;
    asm("tanh.approx.f32 %0, %1;" : "=f"(y) : "f"(x));
    return y;
}

// ---- smem weight layout, ALL layers zero-padded to {8,16}x{8,16} ----
#define O_WFM    0      // 8x16
#define O_BFM    128    // 16
#define O_WC1    144    // 16x16
#define O_BC1    400    // 16
#define O_WP1    416    // 16x16 (cols 12..15 zero)
#define O_BP1    672    // 16 (last 4 zero)
#define O_WC2    688    // 16x8 (rows 12..15 zero)
#define O_BC2    816    // 8
#define O_WP2    824    // 8x8 (cols 4..7 zero)
#define O_BP2    888    // 8 (last 4 zero)
#define O_WC3    896    // 8x8 (rows/cols 4..7 zero)
#define O_BC3    960    // 8 (last 4 zero)
#define O_ROT    968    // 4x4
#define O_ENT    984    // 4x4
#define O_CW     1000   // 4
#define SM_FLOATS 1004

// 8-lane cooperative layer: lane q computes outputs [q*NOq, (q+1)*NOq),
// full activation re-assembled via width-8 shuffles.
template<int NI, int NO>
__device__ __forceinline__ void layer8(const float* __restrict__ smw, int woff, int boff,
                                       int q, const float* __restrict__ xin,
                                       float* __restrict__ xout_full)
{
    constexpr int NOq = NO / 8;
    float acc[NOq];
    #pragma unroll
    for (int oo = 0; oo < NOq; oo++) acc[oo] = smw[boff + q * NOq + oo];
    #pragma unroll
    for (int i = 0; i < NI; i++) {
        float xi = xin[i];
        if constexpr (NOq == 2) {
            float2 w = *reinterpret_cast<const float2*>(smw + woff + i * NO + q * 2);
            acc[0] = fmaf(xi, w.x, acc[0]);
            acc[1] = fmaf(xi, w.y, acc[1]);
        } else {
            acc[0] = fmaf(xi, smw[woff + i * NO + q], acc[0]);
        }
    }
    float loc[NOq];
    #pragma unroll
    for (int oo = 0; oo < NOq; oo++) loc[oo] = tanh_hw(acc[oo]);
    #pragma unroll
    for (int i = 0; i < NO; i++)
        xout_full[i] = __shfl_sync(0xffffffffu, loc[i % NOq], i / NOq, 8);
}

__device__ __forceinline__ void stage(float* dst, const float* src, int n, int tid, int nthr) {
    for (int i = tid; i < n; i += nthr) dst[i] = src[i];
}
// copy src[NIr x NOr] into dst with row stride NOp (pad region pre-zeroed)
__device__ __forceinline__ void stage_pad(float* dst, const float* src,
                                          int NIr, int NOr, int NOp, int tid, int nthr) {
    for (int idx = tid; idx < NIr * NOr; idx += nthr) {
        int i = idx / NOr, o = idx % NOr;
        dst[i * NOp + o] = src[idx];
    }
}

// ---------- Kernel A: MLP chain, 8 lanes per row (padded layers) ----------
__global__ void __launch_bounds__(256) k_prep(
                       const float* __restrict__ inp,
                       const float* __restrict__ Wfm, const float* __restrict__ bfm,
                       const float* __restrict__ Wc1, const float* __restrict__ bc1,
                       const float* __restrict__ Wp1, const float* __restrict__ bp1,
                       const float* __restrict__ Wc2, const float* __restrict__ bc2,
                       const float* __restrict__ Wp2, const float* __restrict__ bp2,
                       const float* __restrict__ Wc3, const float* __restrict__ bc3,
                       const float* __restrict__ rot, const float* __restrict__ ent,
                       const float* __restrict__ conv_w)
{
    __shared__ __align__(16) float sm[SM_FLOATS];
    __shared__ float smKn[32];
    int tid = threadIdx.x;

    // zero everything (covers all padding), then stage real values
    for (int i = tid; i < SM_FLOATS; i += 256) sm[i] = 0.f;
    __syncthreads();
    stage(sm + O_WFM, Wfm, 128, tid, 256);
    stage(sm + O_BFM, bfm, 16,  tid, 256);
    stage(sm + O_WC1, Wc1, 256, tid, 256);
    stage(sm + O_BC1, bc1, 16,  tid, 256);
    stage_pad(sm + O_WP1, Wp1, 16, 12, 16, tid, 256);
    stage(sm + O_BP1, bp1, 12,  tid, 256);
    stage_pad(sm + O_WC2, Wc2, 12, 8, 8, tid, 256);
    stage(sm + O_BC2, bc2, 8,   tid, 256);
    stage_pad(sm + O_WP2, Wp2, 8, 4, 8, tid, 256);
    stage(sm + O_BP2, bp2, 4,   tid, 256);
    stage_pad(sm + O_WC3, Wc3, 4, 4, 8, tid, 256);
    stage(sm + O_BC3, bc3, 4,   tid, 256);
    stage(sm + O_ROT, rot, 16,  tid, 256);
    stage(sm + O_ENT, ent, 16,  tid, 256);
    stage(sm + O_CW,  conv_w, 4, tid, 256);
    __syncthreads();

    int r = blockIdx.x * 32 + (tid >> 3);   // row
    int q = tid & 7;                        // lane within row

    float x0[16], x1[16];
    {
        const float4* ip = reinterpret_cast<const float4*>(inp + r * 8);
        float4 v0 = __ldg(ip), v1 = __ldg(ip + 1);
        x0[0]=v0.x; x0[1]=v0.y; x0[2]=v0.z; x0[3]=v0.w;
        x0[4]=v1.x; x0[5]=v1.y; x0[6]=v1.z; x0[7]=v1.w;
    }

    layer8<8, 16>(sm, O_WFM, O_BFM, q, x0, x1);
    layer8<16,16>(sm, O_WC1, O_BC1, q, x1, x0);
    layer8<16,16>(sm, O_WP1, O_BP1, q, x0, x1);   // 12 real + 4 zero outputs
    layer8<16, 8>(sm, O_WC2, O_BC2, q, x1, x0);
    layer8<8,  8>(sm, O_WP2, O_BP2, q, x0, x1);   // 4 real + 4 zero outputs
    layer8<8,  8>(sm, O_WC3, O_BC3, q, x1, x0);   // final x in x0[0..3]

    if (q == 0) {
        float qv[4], kv[4];
        #pragma unroll
        for (int c = 0; c < 4; c++) {
            float sq = 0.f, sk = 0.f;
            #pragma unroll
            for (int i = 0; i < 4; i++) {
                sq = fmaf(x0[i], sm[O_ROT + i * 4 + c], sq);
                sk = fmaf(x0[i], sm[O_ENT + i * 4 + c], sk);
            }
            qv[c] = sq * (0.5f * LOG2E);
            kv[c] = sk;
        }

        gQ4[r] = make_float4(qv[0], qv[1], qv[2], qv[3]);
        float qn = sqrtf(qv[0]*qv[0] + qv[1]*qv[1] + qv[2]*qv[2] + qv[3]*qv[3]);
        gQn[r] = qn;
        float kn = sqrtf(kv[0]*kv[0] + kv[1]*kv[1] + kv[2]*kv[2] + kv[3]*kv[3]);
        smKn[tid >> 3] = kn;

        uint4 kk;
        kk.x = h2u(__floats2half2_rn(kv[0], kv[0]));
        kk.y = h2u(__floats2half2_rn(kv[1], kv[1]));
        kk.z = h2u(__floats2half2_rn(kv[2], kv[2]));
        kk.w = h2u(__floats2half2_rn(kv[3], kv[3]));
        gKh[r] = kk;
        float cc = fmaf(x0[0], sm[O_CW+0], fmaf(x0[1], sm[O_CW+1],
                   fmaf(x0[2], sm[O_CW+2], x0[3] * sm[O_CW+3])));
        gCh[r] = h2u(__floats2half2_rn(cc, cc));
    }
    __syncthreads();
    if (tid == 0) {
        float m = smKn[0];
        #pragma unroll
        for (int i = 1; i < 32; i++) m = fmaxf(m, smKn[i]);
        gKmaxBlk[blockIdx.x] = m;
    }
}

// ---------- Kernel B: streaming attention, full-fp16 inner loop (unchanged) ----------
__global__ void __launch_bounds__(512) k_attn() {
    __shared__ uint4 smK[JMAX];
    __shared__ u32   smC[JMAX];

    int tid   = threadIdx.x;
    int t     = blockIdx.x * 512 + tid;   // 0..RSTRIDE-1
    int slice = blockIdx.y;

    int j0  = (slice * NB) / NSLICE;
    int cnt = ((slice + 1) * NB) / NSLICE - j0;

    if (tid < cnt) {
        smK[tid] = gKh[j0 + tid];
        smC[tid] = gCh[j0 + tid];
    }

    float kmax = 0.f;
    {
        const float4* km4 = reinterpret_cast<const float4*>(gKmaxBlk);
        #pragma unroll
        for (int i = 0; i < NPREPB / 4; i++) {
            float4 v = __ldg(km4 + i);
            kmax = fmaxf(kmax, fmaxf(fmaxf(v.x, v.y), fmaxf(v.z, v.w)));
        }
    }

    __half2 qx[NPAIR], qy[NPAIR], qz[NPAIR], qw[NPAIR], nmh[NPAIR];
    float sA[NPAIR], sB[NPAIR], yA[NPAIR], yB[NPAIR];

    #pragma unroll
    for (int p = 0; p < NPAIR; p++) {
        int r0 = t + (2 * p)     * RSTRIDE;
        int r1 = t + (2 * p + 1) * RSTRIDE;
        float4 qa = gQ4[r0];
        float4 qb = gQ4[r1];
        qx[p] = __floats2half2_rn(qa.x, qb.x);
        qy[p] = __floats2half2_rn(qa.y, qb.y);
        qz[p] = __floats2half2_rn(qa.z, qb.z);
        qw[p] = __floats2half2_rn(qa.w, qb.w);
        nmh[p] = __floats2half2_rn(-gQn[r0] * kmax, -gQn[r1] * kmax);
        sA[p] = 0.f; sB[p] = 0.f; yA[p] = 0.f; yB[p] = 0.f;
    }

    __syncthreads();

    const __half2 hz = __float2half2_rn(0.f);
    int nfull = cnt >> 3;

    for (int c8 = 0; c8 < nfull; c8++) {
        __half2 sh[NPAIR], yh[NPAIR];
        #pragma unroll
        for (int p = 0; p < NPAIR; p++) { sh[p] = hz; yh[p] = hz; }
        int base = c8 * 8;
        #pragma unroll
        for (int u = 0; u < 8; u++) {
            uint4 kk = smK[base + u];
            __half2 kx = u2h(kk.x), ky = u2h(kk.y), kz = u2h(kk.z), kw = u2h(kk.w);
            __half2 ch = u2h(smC[base + u]);
            #pragma unroll
            for (int p = 0; p < NPAIR; p++) {
                __half2 s = __hfma2(qx[p], kx, nmh[p]);
                s = __hfma2(qy[p], ky, s);
                s = __hfma2(qz[p], kz, s);
                s = __hfma2(qw[p], kw, s);
                __half2 e = hexp2_x(s);
                sh[p] = __hadd2(sh[p], e);
                yh[p] = __hfma2(e, ch, yh[p]);
            }
        }
        #pragma unroll
        for (int p = 0; p < NPAIR; p++) {
            sA[p] += __low2float(sh[p]);  sB[p] += __high2float(sh[p]);
            yA[p] += __low2float(yh[p]);  yB[p] += __high2float(yh[p]);
        }
    }
    {
        __half2 sh[NPAIR], yh[NPAIR];
        #pragma unroll
        for (int p = 0; p < NPAIR; p++) { sh[p] = hz; yh[p] = hz; }
        for (int j = nfull * 8; j < cnt; j++) {
            uint4 kk = smK[j];
            __half2 kx = u2h(kk.x), ky = u2h(kk.y), kz = u2h(kk.z), kw = u2h(kk.w);
            __half2 ch = u2h(smC[j]);
            #pragma unroll
            for (int p = 0; p < NPAIR; p++) {
                __half2 s = __hfma2(qx[p], kx, nmh[p]);
                s = __hfma2(qy[p], ky, s);
                s = __hfma2(qz[p], kz, s);
                s = __hfma2(qw[p], kw, s);
                __half2 e = hexp2_x(s);
                sh[p] = __hadd2(sh[p], e);
                yh[p] = __hfma2(e, ch, yh[p]);
            }
        }
        #pragma unroll
        for (int p = 0; p < NPAIR; p++) {
            sA[p] += __low2float(sh[p]);  sB[p] += __high2float(sh[p]);
            yA[p] += __low2float(yh[p]);  yB[p] += __high2float(yh[p]);
        }
    }

    float2* __restrict__ gp2 = reinterpret_cast<float2*>(gP);
    #pragma unroll
    for (int p = 0; p < NPAIR; p++) {
        int r0 = t + (2 * p)     * RSTRIDE;
        int r1 = t + (2 * p + 1) * RSTRIDE;
        gp2[r0 * PSTRIDE + slice] = make_float2(sA[p], yA[p]);
        gp2[r1 * PSTRIDE + slice] = make_float2(sB[p], yB[p]);
    }
}

// ---------- Kernel C: reduce slices (8 lanes/row) + conv-sigmoid + head-sigmoid ----------
__global__ void __launch_bounds__(256) k_tail(
                       const float* __restrict__ conv_b,
                       const float* __restrict__ head_w, const float* __restrict__ head_b,
                       float* __restrict__ out)
{
    int tid = blockIdx.x * 256 + threadIdx.x;
    int row = tid >> 3;          // 8 lanes per row
    int l   = tid & 7;

    const float4* __restrict__ p = gP + row * (PSTRIDE / 2);
    float sum = 0.f, y = 0.f;
    #pragma unroll
    for (int i = l; i < PSTRIDE / 2; i += 8) {
        float4 v = __ldg(p + i);      // {sum0, y0, sum1, y1}
        sum += v.x + v.z;
        y   += v.y + v.w;
    }
    sum += __shfl_xor_sync(0xffffffffu, sum, 1, 8);
    y   += __shfl_xor_sync(0xffffffffu, y,   1, 8);
    sum += __shfl_xor_sync(0xffffffffu, sum, 2, 8);
    y   += __shfl_xor_sync(0xffffffffu, y,   2, 8);
    sum += __shfl_xor_sync(0xffffffffu, sum, 4, 8);
    y   += __shfl_xor_sync(0xffffffffu, y,   4, 8);

    if (l == 0) {
        float z = fmaf(y, 1.f / sum, conv_b[0]);
        float f = 1.f / (1.f + expf(-z));
        float logit = fmaf(f, head_w[0], head_b[0]);
        out[row] = 1.f / (1.f + expf(-logit));
    }
}

extern "C" void kernel_launch(void* const* d_in, const int* in_sizes, int n_in,
                              void* d_out, int out_size)
{
    const float* inp  = (const float*)d_in[0];
    const float* Wfm  = (const float*)d_in[1];
    const float* bfm  = (const float*)d_in[2];
    const float* Wc1  = (const float*)d_in[3];
    const float* bc1  = (const float*)d_in[4];
    const float* Wp1  = (const float*)d_in[5];
    const float* bp1  = (const float*)d_in[6];
    const float* Wc2  = (const float*)d_in[7];
    const float* bc2  = (const float*)d_in[8];
    const float* Wp2  = (const float*)d_in[9];
    const float* bp2  = (const float*)d_in[10];
    const float* Wc3  = (const float*)d_in[11];
    const float* bc3  = (const float*)d_in[12];
    const float* rot  = (const float*)d_in[13];
    const float* ent  = (const float*)d_in[14];
    const float* cw   = (const float*)d_in[15];
    const float* cb   = (const float*)d_in[16];
    const float* hw   = (const float*)d_in[17];
    const float* hb   = (const float*)d_in[18];
    float* out = (float*)d_out;

    k_prep<<<NPREPB, 256>>>(inp, Wfm, bfm, Wc1, bc1, Wp1, bp1,
                            Wc2, bc2, Wp2, bp2, Wc3, bc3, rot, ent, cw);
    dim3 gridB(RSTRIDE / 512, NSLICE);   // 4 x 37 = 148 blocks, 16 warps each
    k_attn<<<gridB, 512>>>();
    k_tail<<<NB * 8 / 256, 256>>>(cb, hw, hb, out);
}

// round 12
// speedup vs baseline: 1.0791x; 1.0791x over previous
#include <cuda_runtime.h>
#include <cuda_fp16.h>
#include <math.h>

#define NB 8192
#define NSLICE 37              // 4 x-groups * 37 slices = 148 blocks = 1 block/SM
#define PSTRIDE 38             // padded partial stride; pad slot stays 0
#define RPT 4                  // rows per thread in attention
#define RSTRIDE (NB / RPT)     // 2048
#define NPAIR (RPT / 2)        // 2 packed row-pairs
#define JMAX 222               // max j per slice
#define NPREPB 128             // prep blocks (64 rows each)
#define LOG2E 1.4426950408889634f

typedef unsigned int u32;

// ---- scratch (device globals; no allocation allowed) ----
__device__ float4 gQ4[NB];                 // q * (0.5*log2e) per row (fp32)
__device__ float  gQn[NB];                 // |q_tilde| per row
__device__ uint4  gKh[NB];                 // {h2(kx,kx), h2(ky,ky), h2(kz,kz), h2(kw,kw)}
__device__ u32    gCh[NB];                 // h2(c,c), c = x . conv_w
__device__ __align__(16) float gKmaxBlk[NPREPB];  // per-prep-block max |k|
__device__ float4 gP[NB * PSTRIDE / 2];    // {sum,y} float2 pairs, padded
__device__ int    gDone[4];                // per-x-group arrival counters (self-resetting)

__device__ __forceinline__ __half2 u2h(u32 v) { __half2 h; *reinterpret_cast<u32*>(&h) = v; return h; }
__device__ __forceinline__ u32 h2u(__half2 h) { return *reinterpret_cast<u32*>(&h); }
__device__ __forceinline__ __half2 hexp2_x(__half2 v) {
    u32 r, s = h2u(v);
    asm("ex2.approx.f16x2 %0, %1;" : "=r"(r) : "r"(s));
    return u2h(r);
}
__device__ __forceinline__ float tanh_hw(float x) {
    float y;
    asm("tanh.approx.f32 %0, %1;" : "=f"(y) : "f"(x));
    return y;
}

// ---- smem weight layout (float offsets) ----
#define O_WFM   0
#define O_BFM   128
#define O_WC1   144
#define O_BC1   400
#define O_WP1   416
#define O_BP1   608
#define O_WC2   620
#define O_BC2   716
#define O_WP2   724
#define O_BP2   756
#define O_WC3   760
#define O_BC3   776
#define O_ROT   780
#define O_ENT   796
#define O_CW    812
#define SM_FLOATS 816

template<int NI, int NO>
__device__ __forceinline__ void layer4(const float* __restrict__ smw, int woff, int boff,
                                       int q, const float* __restrict__ xin,
                                       float* __restrict__ xout_full)
{
    constexpr int NOq = NO / 4;
    float acc[NOq];
    #pragma unroll
    for (int oo = 0; oo < NOq; oo++) acc[oo] = smw[boff + q * NOq + oo];
    #pragma unroll
    for (int i = 0; i < NI; i++) {
        float xi = xin[i];
        if constexpr (NOq == 4) {
            float4 w = *reinterpret_cast<const float4*>(smw + woff + i * NO + q * 4);
            acc[0] = fmaf(xi, w.x, acc[0]);
            acc[1] = fmaf(xi, w.y, acc[1]);
            acc[2] = fmaf(xi, w.z, acc[2]);
            acc[3] = fmaf(xi, w.w, acc[3]);
        } else if constexpr (NOq == 2) {
            float2 w = *reinterpret_cast<const float2*>(smw + woff + i * NO + q * 2);
            acc[0] = fmaf(xi, w.x, acc[0]);
            acc[1] = fmaf(xi, w.y, acc[1]);
        } else {
            #pragma unroll
            for (int oo = 0; oo < NOq; oo++)
                acc[oo] = fmaf(xi, smw[woff + i * NO + q * NOq + oo], acc[oo]);
        }
    }
    float loc[NOq];
    #pragma unroll
    for (int oo = 0; oo < NOq; oo++) loc[oo] = tanh_hw(acc[oo]);
    #pragma unroll
    for (int i = 0; i < NO; i++)
        xout_full[i] = __shfl_sync(0xffffffffu, loc[i % NOq], i / NOq, 4);
}

__device__ __forceinline__ void stage(float* dst, const float* src, int n, int tid, int nthr) {
    for (int i = tid; i < n; i += nthr) dst[i] = src[i];
}

// ---------- Kernel A: MLP chain, 4 lanes per row (R10-proven) ----------
__global__ void __launch_bounds__(256) k_prep(
                       const float* __restrict__ inp,
                       const float* __restrict__ Wfm, const float* __restrict__ bfm,
                       const float* __restrict__ Wc1, const float* __restrict__ bc1,
                       const float* __restrict__ Wp1, const float* __restrict__ bp1,
                       const float* __restrict__ Wc2, const float* __restrict__ bc2,
                       const float* __restrict__ Wp2, const float* __restrict__ bp2,
                       const float* __restrict__ Wc3, const float* __restrict__ bc3,
                       const float* __restrict__ rot, const float* __restrict__ ent,
                       const float* __restrict__ conv_w)
{
    __shared__ __align__(16) float sm[SM_FLOATS];
    __shared__ float smKn[64];
    int tid = threadIdx.x;
    stage(sm + O_WFM, Wfm, 128, tid, 256);
    stage(sm + O_BFM, bfm, 16,  tid, 256);
    stage(sm + O_WC1, Wc1, 256, tid, 256);
    stage(sm + O_BC1, bc1, 16,  tid, 256);
    stage(sm + O_WP1, Wp1, 192, tid, 256);
    stage(sm + O_BP1, bp1, 12,  tid, 256);
    stage(sm + O_WC2, Wc2, 96,  tid, 256);
    stage(sm + O_BC2, bc2, 8,   tid, 256);
    stage(sm + O_WP2, Wp2, 32,  tid, 256);
    stage(sm + O_BP2, bp2, 4,   tid, 256);
    stage(sm + O_WC3, Wc3, 16,  tid, 256);
    stage(sm + O_BC3, bc3, 4,   tid, 256);
    stage(sm + O_ROT, rot, 16,  tid, 256);
    stage(sm + O_ENT, ent, 16,  tid, 256);
    stage(sm + O_CW,  conv_w, 4, tid, 256);
    __syncthreads();

    int r = blockIdx.x * 64 + (tid >> 2);   // row
    int q = tid & 3;                        // lane within row

    float x0[16], x1[16];
    {
        const float4* ip = reinterpret_cast<const float4*>(inp + r * 8);
        float4 v0 = __ldg(ip), v1 = __ldg(ip + 1);
        x0[0]=v0.x; x0[1]=v0.y; x0[2]=v0.z; x0[3]=v0.w;
        x0[4]=v1.x; x0[5]=v1.y; x0[6]=v1.z; x0[7]=v1.w;
    }

    layer4<8, 16>(sm, O_WFM, O_BFM, q, x0, x1);
    layer4<16,16>(sm, O_WC1, O_BC1, q, x1, x0);
    layer4<16,12>(sm, O_WP1, O_BP1, q, x0, x1);
    layer4<12, 8>(sm, O_WC2, O_BC2, q, x1, x0);
    layer4<8,  4>(sm, O_WP2, O_BP2, q, x0, x1);
    layer4<4,  4>(sm, O_WC3, O_BC3, q, x1, x0);   // final x in x0[0..3]

    if (q == 0) {
        float qv[4], kv[4];
        #pragma unroll
        for (int c = 0; c < 4; c++) {
            float sq = 0.f, sk = 0.f;
            #pragma unroll
            for (int i = 0; i < 4; i++) {
                sq = fmaf(x0[i], sm[O_ROT + i * 4 + c], sq);
                sk = fmaf(x0[i], sm[O_ENT + i * 4 + c], sk);
            }
            qv[c] = sq * (0.5f * LOG2E);
            kv[c] = sk;
        }

        gQ4[r] = make_float4(qv[0], qv[1], qv[2], qv[3]);
        float qn = sqrtf(qv[0]*qv[0] + qv[1]*qv[1] + qv[2]*qv[2] + qv[3]*qv[3]);
        gQn[r] = qn;
        float kn = sqrtf(kv[0]*kv[0] + kv[1]*kv[1] + kv[2]*kv[2] + kv[3]*kv[3]);
        smKn[tid >> 2] = kn;

        uint4 kk;
        kk.x = h2u(__floats2half2_rn(kv[0], kv[0]));
        kk.y = h2u(__floats2half2_rn(kv[1], kv[1]));
        kk.z = h2u(__floats2half2_rn(kv[2], kv[2]));
        kk.w = h2u(__floats2half2_rn(kv[3], kv[3]));
        gKh[r] = kk;
        float cc = fmaf(x0[0], sm[O_CW+0], fmaf(x0[1], sm[O_CW+1],
                   fmaf(x0[2], sm[O_CW+2], x0[3] * sm[O_CW+3])));
        gCh[r] = h2u(__floats2half2_rn(cc, cc));
    }
    __syncthreads();
    if (tid == 0) {
        float m = smKn[0];
        #pragma unroll
        for (int i = 1; i < 64; i++) m = fmaxf(m, smKn[i]);
        gKmaxBlk[blockIdx.x] = m;
    }
}

// ---------- Kernel B: fp16 attention + fused arrival-counter tail ----------
__global__ void __launch_bounds__(512) k_attn(
        const float* __restrict__ conv_b,
        const float* __restrict__ head_w, const float* __restrict__ head_b,
        float* __restrict__ out)
{
    __shared__ uint4 smK[JMAX];
    __shared__ u32   smC[JMAX];
    __shared__ int   smLast;

    int tid   = threadIdx.x;
    int x     = blockIdx.x;               // x-group (0..3)
    int t     = x * 512 + tid;            // 0..RSTRIDE-1
    int slice = blockIdx.y;

    int j0  = (slice * NB) / NSLICE;
    int cnt = ((slice + 1) * NB) / NSLICE - j0;

    if (tid < cnt) {
        smK[tid] = gKh[j0 + tid];
        smC[tid] = gCh[j0 + tid];
    }

    float kmax = 0.f;
    {
        const float4* km4 = reinterpret_cast<const float4*>(gKmaxBlk);
        #pragma unroll
        for (int i = 0; i < NPREPB / 4; i++) {
            float4 v = __ldg(km4 + i);
            kmax = fmaxf(kmax, fmaxf(fmaxf(v.x, v.y), fmaxf(v.z, v.w)));
        }
    }

    __half2 qx[NPAIR], qy[NPAIR], qz[NPAIR], qw[NPAIR], nmh[NPAIR];
    float sA[NPAIR], sB[NPAIR], yA[NPAIR], yB[NPAIR];

    #pragma unroll
    for (int p = 0; p < NPAIR; p++) {
        int r0 = t + (2 * p)     * RSTRIDE;
        int r1 = t + (2 * p + 1) * RSTRIDE;
        float4 qa = gQ4[r0];
        float4 qb = gQ4[r1];
        qx[p] = __floats2half2_rn(qa.x, qb.x);
        qy[p] = __floats2half2_rn(qa.y, qb.y);
        qz[p] = __floats2half2_rn(qa.z, qb.z);
        qw[p] = __floats2half2_rn(qa.w, qb.w);
        nmh[p] = __floats2half2_rn(-gQn[r0] * kmax, -gQn[r1] * kmax);
        sA[p] = 0.f; sB[p] = 0.f; yA[p] = 0.f; yB[p] = 0.f;
    }

    __syncthreads();

    const __half2 hz = __float2half2_rn(0.f);
    int nfull = cnt >> 3;

    for (int c8 = 0; c8 < nfull; c8++) {
        __half2 sh[NPAIR], yh[NPAIR];
        #pragma unroll
        for (int p = 0; p < NPAIR; p++) { sh[p] = hz; yh[p] = hz; }
        int base = c8 * 8;
        #pragma unroll
        for (int u = 0; u < 8; u++) {
            uint4 kk = smK[base + u];
            __half2 kx = u2h(kk.x), ky = u2h(kk.y), kz = u2h(kk.z), kw = u2h(kk.w);
            __half2 ch = u2h(smC[base + u]);
            #pragma unroll
            for (int p = 0; p < NPAIR; p++) {
                __half2 s = __hfma2(qx[p], kx, nmh[p]);
                s = __hfma2(qy[p], ky, s);
                s = __hfma2(qz[p], kz, s);
                s = __hfma2(qw[p], kw, s);
                __half2 e = hexp2_x(s);
                sh[p] = __hadd2(sh[p], e);
                yh[p] = __hfma2(e, ch, yh[p]);
            }
        }
        #pragma unroll
        for (int p = 0; p < NPAIR; p++) {
            sA[p] += __low2float(sh[p]);  sB[p] += __high2float(sh[p]);
            yA[p] += __low2float(yh[p]);  yB[p] += __high2float(yh[p]);
        }
    }
    {
        __half2 sh[NPAIR], yh[NPAIR];
        #pragma unroll
        for (int p = 0; p < NPAIR; p++) { sh[p] = hz; yh[p] = hz; }
        for (int j = nfull * 8; j < cnt; j++) {
            uint4 kk = smK[j];
            __half2 kx = u2h(kk.x), ky = u2h(kk.y), kz = u2h(kk.z), kw = u2h(kk.w);
            __half2 ch = u2h(smC[j]);
            #pragma unroll
            for (int p = 0; p < NPAIR; p++) {
                __half2 s = __hfma2(qx[p], kx, nmh[p]);
                s = __hfma2(qy[p], ky, s);
                s = __hfma2(qz[p], kz, s);
                s = __hfma2(qw[p], kw, s);
                __half2 e = hexp2_x(s);
                sh[p] = __hadd2(sh[p], e);
                yh[p] = __hfma2(e, ch, yh[p]);
            }
        }
        #pragma unroll
        for (int p = 0; p < NPAIR; p++) {
            sA[p] += __low2float(sh[p]);  sB[p] += __high2float(sh[p]);
            yA[p] += __low2float(yh[p]);  yB[p] += __high2float(yh[p]);
        }
    }

    float2* __restrict__ gp2 = reinterpret_cast<float2*>(gP);
    #pragma unroll
    for (int p = 0; p < NPAIR; p++) {
        int r0 = t + (2 * p)     * RSTRIDE;
        int r1 = t + (2 * p + 1) * RSTRIDE;
        gp2[r0 * PSTRIDE + slice] = make_float2(sA[p], yA[p]);
        gp2[r1 * PSTRIDE + slice] = make_float2(sB[p], yB[p]);
    }

    // ---- fused tail: last-arriving block of this x-group reduces + writes out ----
    __threadfence();                        // make this block's partials visible
    __syncthreads();                        // all threads' stores+fences done
    if (tid == 0) {
        int v = atomicAdd(&gDone[x], 1);
        smLast = (v == NSLICE - 1);
    }
    __syncthreads();

    if (smLast) {
        // value-deterministic: fixed-order sum over all 37 slice partials per row
        float cb0 = conv_b[0], hw0 = head_w[0], hb0 = head_b[0];
        #pragma unroll
        for (int m = 0; m < RPT; m++) {
            int row = t + m * RSTRIDE;
            const float4* __restrict__ p = gP + row * (PSTRIDE / 2);
            float sum = 0.f, y = 0.f;
            #pragma unroll
            for (int i = 0; i < PSTRIDE / 2; i++) {
                float4 v = __ldg(p + i);    // {sum0, y0, sum1, y1}; pad slot is 0
                sum += v.x + v.z;
                y   += v.y + v.w;
            }
            float z = fmaf(y, 1.f / sum, cb0);
            float f = 1.f / (1.f + expf(-z));
            float logit = fmaf(f, hw0, hb0);
            out[row] = 1.f / (1.f + expf(-logit));
        }
        __syncthreads();
        if (tid == 0) gDone[x] = 0;         // reset for next graph replay
    }
}

extern "C" void kernel_launch(void* const* d_in, const int* in_sizes, int n_in,
                              void* d_out, int out_size)
{
    const float* inp  = (const float*)d_in[0];
    const float* Wfm  = (const float*)d_in[1];
    const float* bfm  = (const float*)d_in[2];
    const float* Wc1  = (const float*)d_in[3];
    const float* bc1  = (const float*)d_in[4];
    const float* Wp1  = (const float*)d_in[5];
    const float* bp1  = (const float*)d_in[6];
    const float* Wc2  = (const float*)d_in[7];
    const float* bc2  = (const float*)d_in[8];
    const float* Wp2  = (const float*)d_in[9];
    const float* bp2  = (const float*)d_in[10];
    const float* Wc3  = (const float*)d_in[11];
    const float* bc3  = (const float*)d_in[12];
    const float* rot  = (const float*)d_in[13];
    const float* ent  = (const float*)d_in[14];
    const float* cw   = (const float*)d_in[15];
    const float* cb   = (const float*)d_in[16];
    const float* hw   = (const float*)d_in[17];
    const float* hb   = (const float*)d_in[18];
    float* out = (float*)d_out;

    k_prep<<<NPREPB, 256>>>(inp, Wfm, bfm, Wc1, bc1, Wp1, bp1,
                            Wc2, bc2, Wp2, bp2, Wc3, bc3, rot, ent, cw);
    dim3 gridB(RSTRIDE / 512, NSLICE);   // 4 x 37 = 148 blocks, 16 warps each
    k_attn<<<gridB, 512>>>(cb, hw, hb, out);
}

// round 13
// speedup vs baseline: 1.5140x; 1.4030x over previous
#include <cuda_runtime.h>
#include <cuda_fp16.h>
#include <math.h>

#define NB 8192
#define NSLICE 37              // 4 x-blocks * 37 slices = 148 blocks = 1 block/SM
#define PSTRIDE 38             // padded partial stride; pad slot stays 0
#define RPT 4                  // rows per thread in attention
#define RSTRIDE (NB / RPT)     // 2048
#define NPAIR (RPT / 2)        // 2 packed row-pairs
#define JMAX 222               // max j per slice
#define NPREPB 256             // prep blocks (32 rows each) — covers all SMs, 2x warps
#define LOG2E 1.4426950408889634f

typedef unsigned int u32;

// ---- scratch (device globals; no allocation allowed) ----
__device__ float4 gQ4[NB];                 // q * (0.5*log2e) per row (fp32)
__device__ float  gQn[NB];                 // |q_tilde| per row
__device__ uint4  gKh[NB];                 // {h2(kx,kx), h2(ky,ky), h2(kz,kz), h2(kw,kw)}
__device__ u32    gCh[NB];                 // h2(c,c), c = x . conv_w
__device__ __align__(16) float gKmaxBlk[NPREPB];  // per-prep-block max |k|
__device__ float4 gP[NB * PSTRIDE / 2];    // {sum,y} float2 pairs, padded

__device__ __forceinline__ __half2 u2h(u32 v) { __half2 h; *reinterpret_cast<u32*>(&h) = v; return h; }
__device__ __forceinline__ u32 h2u(__half2 h) { return *reinterpret_cast<u32*>(&h); }
__device__ __forceinline__ __half2 hexp2_x(__half2 v) {
    u32 r, s = h2u(v);
    asm("ex2.approx.f16x2 %0, %1;" : "=r"(r) : "r"(s));
    return u2h(r);
}
__device__ __forceinline__ float tanh_hw(float x) {
    float y;
    asm("tanh.approx.f32 %0, %1;" : "=f"(y) : "f"(x));
    return y;
}

// ---- smem weight layout (float offsets) ----
#define O_WFM   0
#define O_BFM   128
#define O_WC1   144
#define O_BC1   400
#define O_WP1   416
#define O_BP1   608
#define O_WC2   620
#define O_BC2   716
#define O_WP2   724
#define O_BP2   756
#define O_WC3   760
#define O_BC3   776
#define O_ROT   780
#define O_ENT   796
#define O_CW    812
#define SM_FLOATS 816

template<int NI, int NO>
__device__ __forceinline__ void layer4(const float* __restrict__ smw, int woff, int boff,
                                       int q, const float* __restrict__ xin,
                                       float* __restrict__ xout_full)
{
    constexpr int NOq = NO / 4;
    float acc[NOq];
    #pragma unroll
    for (int oo = 0; oo < NOq; oo++) acc[oo] = smw[boff + q * NOq + oo];
    #pragma unroll
    for (int i = 0; i < NI; i++) {
        float xi = xin[i];
        if constexpr (NOq == 4) {
            float4 w = *reinterpret_cast<const float4*>(smw + woff + i * NO + q * 4);
            acc[0] = fmaf(xi, w.x, acc[0]);
            acc[1] = fmaf(xi, w.y, acc[1]);
            acc[2] = fmaf(xi, w.z, acc[2]);
            acc[3] = fmaf(xi, w.w, acc[3]);
        } else if constexpr (NOq == 2) {
            float2 w = *reinterpret_cast<const float2*>(smw + woff + i * NO + q * 2);
            acc[0] = fmaf(xi, w.x, acc[0]);
            acc[1] = fmaf(xi, w.y, acc[1]);
        } else {
            #pragma unroll
            for (int oo = 0; oo < NOq; oo++)
                acc[oo] = fmaf(xi, smw[woff + i * NO + q * NOq + oo], acc[oo]);
        }
    }
    float loc[NOq];
    #pragma unroll
    for (int oo = 0; oo < NOq; oo++) loc[oo] = tanh_hw(acc[oo]);
    #pragma unroll
    for (int i = 0; i < NO; i++)
        xout_full[i] = __shfl_sync(0xffffffffu, loc[i % NOq], i / NOq, 4);
}

__device__ __forceinline__ void stage(float* dst, const float* src, int n, int tid, int nthr) {
    for (int i = tid; i < n; i += nthr) dst[i] = src[i];
}

// ---------- Kernel A: MLP chain, 4 lanes per row, 256 blocks x 32 rows ----------
__global__ void __launch_bounds__(128) k_prep(
                       const float* __restrict__ inp,
                       const float* __restrict__ Wfm, const float* __restrict__ bfm,
                       const float* __restrict__ Wc1, const float* __restrict__ bc1,
                       const float* __restrict__ Wp1, const float* __restrict__ bp1,
                       const float* __restrict__ Wc2, const float* __restrict__ bc2,
                       const float* __restrict__ Wp2, const float* __restrict__ bp2,
                       const float* __restrict__ Wc3, const float* __restrict__ bc3,
                       const float* __restrict__ rot, const float* __restrict__ ent,
                       const float* __restrict__ conv_w)
{
    __shared__ __align__(16) float sm[SM_FLOATS];
    __shared__ float smKn[32];
    int tid = threadIdx.x;
    stage(sm + O_WFM, Wfm, 128, tid, 128);
    stage(sm + O_BFM, bfm, 16,  tid, 128);
    stage(sm + O_WC1, Wc1, 256, tid, 128);
    stage(sm + O_BC1, bc1, 16,  tid, 128);
    stage(sm + O_WP1, Wp1, 192, tid, 128);
    stage(sm + O_BP1, bp1, 12,  tid, 128);
    stage(sm + O_WC2, Wc2, 96,  tid, 128);
    stage(sm + O_BC2, bc2, 8,   tid, 128);
    stage(sm + O_WP2, Wp2, 32,  tid, 128);
    stage(sm + O_BP2, bp2, 4,   tid, 128);
    stage(sm + O_WC3, Wc3, 16,  tid, 128);
    stage(sm + O_BC3, bc3, 4,   tid, 128);
    stage(sm + O_ROT, rot, 16,  tid, 128);
    stage(sm + O_ENT, ent, 16,  tid, 128);
    stage(sm + O_CW,  conv_w, 4, tid, 128);
    __syncthreads();

    int r = blockIdx.x * 32 + (tid >> 2);   // row
    int q = tid & 3;                        // lane within row

    float x0[16], x1[16];
    {
        const float4* ip = reinterpret_cast<const float4*>(inp + r * 8);
        float4 v0 = __ldg(ip), v1 = __ldg(ip + 1);
        x0[0]=v0.x; x0[1]=v0.y; x0[2]=v0.z; x0[3]=v0.w;
        x0[4]=v1.x; x0[5]=v1.y; x0[6]=v1.z; x0[7]=v1.w;
    }

    layer4<8, 16>(sm, O_WFM, O_BFM, q, x0, x1);
    layer4<16,16>(sm, O_WC1, O_BC1, q, x1, x0);
    layer4<16,12>(sm, O_WP1, O_BP1, q, x0, x1);
    layer4<12, 8>(sm, O_WC2, O_BC2, q, x1, x0);
    layer4<8,  4>(sm, O_WP2, O_BP2, q, x0, x1);
    layer4<4,  4>(sm, O_WC3, O_BC3, q, x1, x0);   // final x in x0[0..3]

    if (q == 0) {
        float qv[4], kv[4];
        #pragma unroll
        for (int c = 0; c < 4; c++) {
            float sq = 0.f, sk = 0.f;
            #pragma unroll
            for (int i = 0; i < 4; i++) {
                sq = fmaf(x0[i], sm[O_ROT + i * 4 + c], sq);
                sk = fmaf(x0[i], sm[O_ENT + i * 4 + c], sk);
            }
            qv[c] = sq * (0.5f * LOG2E);
            kv[c] = sk;
        }

        gQ4[r] = make_float4(qv[0], qv[1], qv[2], qv[3]);
        float qn = sqrtf(qv[0]*qv[0] + qv[1]*qv[1] + qv[2]*qv[2] + qv[3]*qv[3]);
        gQn[r] = qn;
        float kn = sqrtf(kv[0]*kv[0] + kv[1]*kv[1] + kv[2]*kv[2] + kv[3]*kv[3]);
        smKn[tid >> 2] = kn;

        uint4 kk;
        kk.x = h2u(__floats2half2_rn(kv[0], kv[0]));
        kk.y = h2u(__floats2half2_rn(kv[1], kv[1]));
        kk.z = h2u(__floats2half2_rn(kv[2], kv[2]));
        kk.w = h2u(__floats2half2_rn(kv[3], kv[3]));
        gKh[r] = kk;
        float cc = fmaf(x0[0], sm[O_CW+0], fmaf(x0[1], sm[O_CW+1],
                   fmaf(x0[2], sm[O_CW+2], x0[3] * sm[O_CW+3])));
        gCh[r] = h2u(__floats2half2_rn(cc, cc));
    }
    __syncthreads();
    if (tid == 0) {
        float m = smKn[0];
        #pragma unroll
        for (int i = 1; i < 32; i++) m = fmaxf(m, smKn[i]);
        gKmaxBlk[blockIdx.x] = m;
    }
}

// ---------- Kernel B: streaming attention, full-fp16 inner loop (R10-proven) ----------
__global__ void __launch_bounds__(512) k_attn() {
    __shared__ uint4 smK[JMAX];
    __shared__ u32   smC[JMAX];

    int tid   = threadIdx.x;
    int t     = blockIdx.x * 512 + tid;   // 0..RSTRIDE-1
    int slice = blockIdx.y;

    int j0  = (slice * NB) / NSLICE;
    int cnt = ((slice + 1) * NB) / NSLICE - j0;

    if (tid < cnt) {
        smK[tid] = gKh[j0 + tid];
        smC[tid] = gCh[j0 + tid];
    }

    float kmax = 0.f;
    {
        const float4* km4 = reinterpret_cast<const float4*>(gKmaxBlk);
        #pragma unroll
        for (int i = 0; i < NPREPB / 4; i++) {
            float4 v = __ldg(km4 + i);
            kmax = fmaxf(kmax, fmaxf(fmaxf(v.x, v.y), fmaxf(v.z, v.w)));
        }
    }

    __half2 qx[NPAIR], qy[NPAIR], qz[NPAIR], qw[NPAIR], nmh[NPAIR];
    float sA[NPAIR], sB[NPAIR], yA[NPAIR], yB[NPAIR];

    #pragma unroll
    for (int p = 0; p < NPAIR; p++) {
        int r0 = t + (2 * p)     * RSTRIDE;
        int r1 = t + (2 * p + 1) * RSTRIDE;
        float4 qa = gQ4[r0];
        float4 qb = gQ4[r1];
        qx[p] = __floats2half2_rn(qa.x, qb.x);
        qy[p] = __floats2half2_rn(qa.y, qb.y);
        qz[p] = __floats2half2_rn(qa.z, qb.z);
        qw[p] = __floats2half2_rn(qa.w, qb.w);
        nmh[p] = __floats2half2_rn(-gQn[r0] * kmax, -gQn[r1] * kmax);
        sA[p] = 0.f; sB[p] = 0.f; yA[p] = 0.f; yB[p] = 0.f;
    }

    __syncthreads();

    const __half2 hz = __float2half2_rn(0.f);
    int nfull = cnt >> 3;

    for (int c8 = 0; c8 < nfull; c8++) {
        __half2 sh[NPAIR], yh[NPAIR];
        #pragma unroll
        for (int p = 0; p < NPAIR; p++) { sh[p] = hz; yh[p] = hz; }
        int base = c8 * 8;
        #pragma unroll
        for (int u = 0; u < 8; u++) {
            uint4 kk = smK[base + u];
            __half2 kx = u2h(kk.x), ky = u2h(kk.y), kz = u2h(kk.z), kw = u2h(kk.w);
            __half2 ch = u2h(smC[base + u]);
            #pragma unroll
            for (int p = 0; p < NPAIR; p++) {
                __half2 s = __hfma2(qx[p], kx, nmh[p]);
                s = __hfma2(qy[p], ky, s);
                s = __hfma2(qz[p], kz, s);
                s = __hfma2(qw[p], kw, s);
                __half2 e = hexp2_x(s);
                sh[p] = __hadd2(sh[p], e);
                yh[p] = __hfma2(e, ch, yh[p]);
            }
        }
        #pragma unroll
        for (int p = 0; p < NPAIR; p++) {
            sA[p] += __low2float(sh[p]);  sB[p] += __high2float(sh[p]);
            yA[p] += __low2float(yh[p]);  yB[p] += __high2float(yh[p]);
        }
    }
    {
        __half2 sh[NPAIR], yh[NPAIR];
        #pragma unroll
        for (int p = 0; p < NPAIR; p++) { sh[p] = hz; yh[p] = hz; }
        for (int j = nfull * 8; j < cnt; j++) {
            uint4 kk = smK[j];
            __half2 kx = u2h(kk.x), ky = u2h(kk.y), kz = u2h(kk.z), kw = u2h(kk.w);
            __half2 ch = u2h(smC[j]);
            #pragma unroll
            for (int p = 0; p < NPAIR; p++) {
                __half2 s = __hfma2(qx[p], kx, nmh[p]);
                s = __hfma2(qy[p], ky, s);
                s = __hfma2(qz[p], kz, s);
                s = __hfma2(qw[p], kw, s);
                __half2 e = hexp2_x(s);
                sh[p] = __hadd2(sh[p], e);
                yh[p] = __hfma2(e, ch, yh[p]);
            }
        }
        #pragma unroll
        for (int p = 0; p < NPAIR; p++) {
            sA[p] += __low2float(sh[p]);  sB[p] += __high2float(sh[p]);
            yA[p] += __low2float(yh[p]);  yB[p] += __high2float(yh[p]);
        }
    }

    float2* __restrict__ gp2 = reinterpret_cast<float2*>(gP);
    #pragma unroll
    for (int p = 0; p < NPAIR; p++) {
        int r0 = t + (2 * p)     * RSTRIDE;
        int r1 = t + (2 * p + 1) * RSTRIDE;
        gp2[r0 * PSTRIDE + slice] = make_float2(sA[p], yA[p]);
        gp2[r1 * PSTRIDE + slice] = make_float2(sB[p], yB[p]);
    }
}

// ---------- Kernel C: reduce slices (4 lanes/row) + conv-sigmoid + head-sigmoid ----------
__global__ void __launch_bounds__(256) k_tail(
                       const float* __restrict__ conv_b,
                       const float* __restrict__ head_w, const float* __restrict__ head_b,
                       float* __restrict__ out)
{
    int tid = blockIdx.x * 256 + threadIdx.x;
    int row = tid >> 2;          // 4 lanes per row
    int l   = tid & 3;

    const float4* __restrict__ p = gP + row * (PSTRIDE / 2);
    float sum = 0.f, y = 0.f;
    #pragma unroll
    for (int i = l; i < PSTRIDE / 2; i += 4) {
        float4 v = __ldg(p + i);      // {sum0, y0, sum1, y1}
        sum += v.x + v.z;
        y   += v.y + v.w;
    }
    sum += __shfl_xor_sync(0xffffffffu, sum, 1, 4);
    y   += __shfl_xor_sync(0xffffffffu, y,   1, 4);
    sum += __shfl_xor_sync(0xffffffffu, sum, 2, 4);
    y   += __shfl_xor_sync(0xffffffffu, y,   2, 4);

    if (l == 0) {
        float z = fmaf(y, 1.f / sum, conv_b[0]);
        float f = 1.f / (1.f + expf(-z));
        float logit = fmaf(f, head_w[0], head_b[0]);
        out[row] = 1.f / (1.f + expf(-logit));
    }
}

extern "C" void kernel_launch(void* const* d_in, const int* in_sizes, int n_in,
                              void* d_out, int out_size)
{
    const float* inp  = (const float*)d_in[0];
    const float* Wfm  = (const float*)d_in[1];
    const float* bfm  = (const float*)d_in[2];
    const float* Wc1  = (const float*)d_in[3];
    const float* bc1  = (const float*)d_in[4];
    const float* Wp1  = (const float*)d_in[5];
    const float* bp1  = (const float*)d_in[6];
    const float* Wc2  = (const float*)d_in[7];
    const float* bc2  = (const float*)d_in[8];
    const float* Wp2  = (const float*)d_in[9];
    const float* bp2  = (const float*)d_in[10];
    const float* Wc3  = (const float*)d_in[11];
    const float* bc3  = (const float*)d_in[12];
    const float* rot  = (const float*)d_in[13];
    const float* ent  = (const float*)d_in[14];
    const float* cw   = (const float*)d_in[15];
    const float* cb   = (const float*)d_in[16];
    const float* hw   = (const float*)d_in[17];
    const float* hb   = (const float*)d_in[18];
    float* out = (float*)d_out;

    k_prep<<<NPREPB, 128>>>(inp, Wfm, bfm, Wc1, bc1, Wp1, bp1,
                            Wc2, bc2, Wp2, bp2, Wc3, bc3, rot, ent, cw);
    dim3 gridB(RSTRIDE / 512, NSLICE);   // 4 x 37 = 148 blocks, 16 warps each
    k_attn<<<gridB, 512>>>();
    k_tail<<<NB * 4 / 256, 256>>>(cb, hw, hb, out);
}

// round 14
// speedup vs baseline: 1.5158x; 1.0012x over previous
#include <cuda_runtime.h>
#include <cuda_fp16.h>
#include <math.h>

#define NB 8192
#define NSLICE 37              // 4 x-blocks * 37 slices = 148 blocks = 1 block/SM
#define PSTRIDE 38             // padded partial stride; pad slot stays 0
#define RPT 4                  // rows per thread in attention
#define RSTRIDE (NB / RPT)     // 2048
#define NPAIR (RPT / 2)        // 2 packed row-pairs
#define JMAX 222               // max j per slice
#define NPREPB 128             // prep blocks (64 rows each, 2x redundant groups)
#define LOG2E 1.4426950408889634f

typedef unsigned int u32;

// ---- scratch (device globals; no allocation allowed) ----
__device__ float4 gQ4[NB];                 // q * (0.5*log2e) per row (fp32)
__device__ float  gQn[NB];                 // |q_tilde| per row
__device__ uint4  gKh[NB];                 // {h2(kx,kx), h2(ky,ky), h2(kz,kz), h2(kw,kw)}
__device__ u32    gCh[NB];                 // h2(c,c), c = x . conv_w
__device__ __align__(16) float gKmaxBlk[NPREPB];  // per-prep-block max |k|
__device__ float4 gP[NB * PSTRIDE / 2];    // {sum,y} float2 pairs, padded

__device__ __forceinline__ __half2 u2h(u32 v) { __half2 h; *reinterpret_cast<u32*>(&h) = v; return h; }
__device__ __forceinline__ u32 h2u(__half2 h) { return *reinterpret_cast<u32*>(&h); }
__device__ __forceinline__ __half2 hexp2_x(__half2 v) {
    u32 r, s = h2u(v);
    asm("ex2.approx.f16x2 %0, %1;" : "=r"(r) : "r"(s));
    return u2h(r);
}
__device__ __forceinline__ float tanh_hw(float x) {
    float y;
    asm("tanh.approx.f32 %0, %1;" : "=f"(y) : "f"(x));
    return y;
}

// ---- smem weight layout (float offsets) ----
#define O_WFM   0
#define O_BFM   128
#define O_WC1   144
#define O_BC1   400
#define O_WP1   416
#define O_BP1   608
#define O_WC2   620
#define O_BC2   716
#define O_WP2   724
#define O_BP2   756
#define O_WC3   760
#define O_BC3   776
#define O_ROT   780
#define O_ENT   796
#define O_CW    812
#define SM_FLOATS 816

template<int NI, int NO>
__device__ __forceinline__ void layer4(const float* __restrict__ smw, int woff, int boff,
                                       int q, const float* __restrict__ xin,
                                       float* __restrict__ xout_full)
{
    constexpr int NOq = NO / 4;
    float acc[NOq];
    #pragma unroll
    for (int oo = 0; oo < NOq; oo++) acc[oo] = smw[boff + q * NOq + oo];
    #pragma unroll
    for (int i = 0; i < NI; i++) {
        float xi = xin[i];
        if constexpr (NOq == 4) {
            float4 w = *reinterpret_cast<const float4*>(smw + woff + i * NO + q * 4);
            acc[0] = fmaf(xi, w.x, acc[0]);
            acc[1] = fmaf(xi, w.y, acc[1]);
            acc[2] = fmaf(xi, w.z, acc[2]);
            acc[3] = fmaf(xi, w.w, acc[3]);
        } else if constexpr (NOq == 2) {
            float2 w = *reinterpret_cast<const float2*>(smw + woff + i * NO + q * 2);
            acc[0] = fmaf(xi, w.x, acc[0]);
            acc[1] = fmaf(xi, w.y, acc[1]);
        } else {
            #pragma unroll
            for (int oo = 0; oo < NOq; oo++)
                acc[oo] = fmaf(xi, smw[woff + i * NO + q * NOq + oo], acc[oo]);
        }
    }
    float loc[NOq];
    #pragma unroll
    for (int oo = 0; oo < NOq; oo++) loc[oo] = tanh_hw(acc[oo]);
    #pragma unroll
    for (int i = 0; i < NO; i++)
        xout_full[i] = __shfl_sync(0xffffffffu, loc[i % NOq], i / NOq, 4);
}

__device__ __forceinline__ void stage(float* dst, const float* src, int n, int tid, int nthr) {
    for (int i = tid; i < n; i += nthr) dst[i] = src[i];
}

// ---------- Kernel A: MLP chain, 4 lanes/row, 2x redundant groups for occupancy ----------
// 512 threads = 64 rows * 8 threads; threads (tid>>2)&1==1 duplicate the compute
// (free: FMA pipe is ~3% busy, kernel is latency-bound) and write nothing.
__global__ void __launch_bounds__(512) k_prep(
                       const float* __restrict__ inp,
                       const float* __restrict__ Wfm, const float* __restrict__ bfm,
                       const float* __restrict__ Wc1, const float* __restrict__ bc1,
                       const float* __restrict__ Wp1, const float* __restrict__ bp1,
                       const float* __restrict__ Wc2, const float* __restrict__ bc2,
                       const float* __restrict__ Wp2, const float* __restrict__ bp2,
                       const float* __restrict__ Wc3, const float* __restrict__ bc3,
                       const float* __restrict__ rot, const float* __restrict__ ent,
                       const float* __restrict__ conv_w)
{
    __shared__ __align__(16) float sm[SM_FLOATS];
    __shared__ float smKn[64];
    int tid = threadIdx.x;
    stage(sm + O_WFM, Wfm, 128, tid, 512);
    stage(sm + O_BFM, bfm, 16,  tid, 512);
    stage(sm + O_WC1, Wc1, 256, tid, 512);
    stage(sm + O_BC1, bc1, 16,  tid, 512);
    stage(sm + O_WP1, Wp1, 192, tid, 512);
    stage(sm + O_BP1, bp1, 12,  tid, 512);
    stage(sm + O_WC2, Wc2, 96,  tid, 512);
    stage(sm + O_BC2, bc2, 8,   tid, 512);
    stage(sm + O_WP2, Wp2, 32,  tid, 512);
    stage(sm + O_BP2, bp2, 4,   tid, 512);
    stage(sm + O_WC3, Wc3, 16,  tid, 512);
    stage(sm + O_BC3, bc3, 4,   tid, 512);
    stage(sm + O_ROT, rot, 16,  tid, 512);
    stage(sm + O_ENT, ent, 16,  tid, 512);
    stage(sm + O_CW,  conv_w, 4, tid, 512);
    __syncthreads();

    int r   = blockIdx.x * 64 + (tid >> 3);   // row (each row: 8 threads = 2 groups)
    int grp = (tid >> 2) & 1;                 // redundant group (only grp 0 writes)
    int q   = tid & 3;                        // lane within 4-lane group

    float x0[16], x1[16];
    {
        const float4* ip = reinterpret_cast<const float4*>(inp + r * 8);
        float4 v0 = __ldg(ip), v1 = __ldg(ip + 1);
        x0[0]=v0.x; x0[1]=v0.y; x0[2]=v0.z; x0[3]=v0.w;
        x0[4]=v1.x; x0[5]=v1.y; x0[6]=v1.z; x0[7]=v1.w;
    }

    layer4<8, 16>(sm, O_WFM, O_BFM, q, x0, x1);
    layer4<16,16>(sm, O_WC1, O_BC1, q, x1, x0);
    layer4<16,12>(sm, O_WP1, O_BP1, q, x0, x1);
    layer4<12, 8>(sm, O_WC2, O_BC2, q, x1, x0);
    layer4<8,  4>(sm, O_WP2, O_BP2, q, x0, x1);
    layer4<4,  4>(sm, O_WC3, O_BC3, q, x1, x0);   // final x in x0[0..3]

    if (q == 0 && grp == 0) {
        float qv[4], kv[4];
        #pragma unroll
        for (int c = 0; c < 4; c++) {
            float sq = 0.f, sk = 0.f;
            #pragma unroll
            for (int i = 0; i < 4; i++) {
                sq = fmaf(x0[i], sm[O_ROT + i * 4 + c], sq);
                sk = fmaf(x0[i], sm[O_ENT + i * 4 + c], sk);
            }
            qv[c] = sq * (0.5f * LOG2E);
            kv[c] = sk;
        }

        gQ4[r] = make_float4(qv[0], qv[1], qv[2], qv[3]);
        float qn = sqrtf(qv[0]*qv[0] + qv[1]*qv[1] + qv[2]*qv[2] + qv[3]*qv[3]);
        gQn[r] = qn;
        float kn = sqrtf(kv[0]*kv[0] + kv[1]*kv[1] + kv[2]*kv[2] + kv[3]*kv[3]);
        smKn[tid >> 3] = kn;

        uint4 kk;
        kk.x = h2u(__floats2half2_rn(kv[0], kv[0]));
        kk.y = h2u(__floats2half2_rn(kv[1], kv[1]));
        kk.z = h2u(__floats2half2_rn(kv[2], kv[2]));
        kk.w = h2u(__floats2half2_rn(kv[3], kv[3]));
        gKh[r] = kk;
        float cc = fmaf(x0[0], sm[O_CW+0], fmaf(x0[1], sm[O_CW+1],
                   fmaf(x0[2], sm[O_CW+2], x0[3] * sm[O_CW+3])));
        gCh[r] = h2u(__floats2half2_rn(cc, cc));
    }
    __syncthreads();
    if (tid == 0) {
        float m = smKn[0];
        #pragma unroll
        for (int i = 1; i < 64; i++) m = fmaxf(m, smKn[i]);
        gKmaxBlk[blockIdx.x] = m;
    }
}

// ---------- Kernel B: streaming attention, full-fp16 inner loop (R10-proven) ----------
__global__ void __launch_bounds__(512) k_attn() {
    __shared__ uint4 smK[JMAX];
    __shared__ u32   smC[JMAX];

    int tid   = threadIdx.x;
    int t     = blockIdx.x * 512 + tid;   // 0..RSTRIDE-1
    int slice = blockIdx.y;

    int j0  = (slice * NB) / NSLICE;
    int cnt = ((slice + 1) * NB) / NSLICE - j0;

    if (tid < cnt) {
        smK[tid] = gKh[j0 + tid];
        smC[tid] = gCh[j0 + tid];
    }

    float kmax = 0.f;
    {
        const float4* km4 = reinterpret_cast<const float4*>(gKmaxBlk);
        #pragma unroll
        for (int i = 0; i < NPREPB / 4; i++) {
            float4 v = __ldg(km4 + i);
            kmax = fmaxf(kmax, fmaxf(fmaxf(v.x, v.y), fmaxf(v.z, v.w)));
        }
    }

    __half2 qx[NPAIR], qy[NPAIR], qz[NPAIR], qw[NPAIR], nmh[NPAIR];
    float sA[NPAIR], sB[NPAIR], yA[NPAIR], yB[NPAIR];

    #pragma unroll
    for (int p = 0; p < NPAIR; p++) {
        int r0 = t + (2 * p)     * RSTRIDE;
        int r1 = t + (2 * p + 1) * RSTRIDE;
        float4 qa = gQ4[r0];
        float4 qb = gQ4[r1];
        qx[p] = __floats2half2_rn(qa.x, qb.x);
        qy[p] = __floats2half2_rn(qa.y, qb.y);
        qz[p] = __floats2half2_rn(qa.z, qb.z);
        qw[p] = __floats2half2_rn(qa.w, qb.w);
        nmh[p] = __floats2half2_rn(-gQn[r0] * kmax, -gQn[r1] * kmax);
        sA[p] = 0.f; sB[p] = 0.f; yA[p] = 0.f; yB[p] = 0.f;
    }

    __syncthreads();

    const __half2 hz = __float2half2_rn(0.f);
    int nfull = cnt >> 3;

    for (int c8 = 0; c8 < nfull; c8++) {
        __half2 sh[NPAIR], yh[NPAIR];
        #pragma unroll
        for (int p = 0; p < NPAIR; p++) { sh[p] = hz; yh[p] = hz; }
        int base = c8 * 8;
        #pragma unroll
        for (int u = 0; u < 8; u++) {
            uint4 kk = smK[base + u];
            __half2 kx = u2h(kk.x), ky = u2h(kk.y), kz = u2h(kk.z), kw = u2h(kk.w);
            __half2 ch = u2h(smC[base + u]);
            #pragma unroll
            for (int p = 0; p < NPAIR; p++) {
                __half2 s = __hfma2(qx[p], kx, nmh[p]);
                s = __hfma2(qy[p], ky, s);
                s = __hfma2(qz[p], kz, s);
                s = __hfma2(qw[p], kw, s);
                __half2 e = hexp2_x(s);
                sh[p] = __hadd2(sh[p], e);
                yh[p] = __hfma2(e, ch, yh[p]);
            }
        }
        #pragma unroll
        for (int p = 0; p < NPAIR; p++) {
            sA[p] += __low2float(sh[p]);  sB[p] += __high2float(sh[p]);
            yA[p] += __low2float(yh[p]);  yB[p] += __high2float(yh[p]);
        }
    }
    {
        __half2 sh[NPAIR], yh[NPAIR];
        #pragma unroll
        for (int p = 0; p < NPAIR; p++) { sh[p] = hz; yh[p] = hz; }
        for (int j = nfull * 8; j < cnt; j++) {
            uint4 kk = smK[j];
            __half2 kx = u2h(kk.x), ky = u2h(kk.y), kz = u2h(kk.z), kw = u2h(kk.w);
            __half2 ch = u2h(smC[j]);
            #pragma unroll
            for (int p = 0; p < NPAIR; p++) {
                __half2 s = __hfma2(qx[p], kx, nmh[p]);
                s = __hfma2(qy[p], ky, s);
                s = __hfma2(qz[p], kz, s);
                s = __hfma2(qw[p], kw, s);
                __half2 e = hexp2_x(s);
                sh[p] = __hadd2(sh[p], e);
                yh[p] = __hfma2(e, ch, yh[p]);
            }
        }
        #pragma unroll
        for (int p = 0; p < NPAIR; p++) {
            sA[p] += __low2float(sh[p]);  sB[p] += __high2float(sh[p]);
            yA[p] += __low2float(yh[p]);  yB[p] += __high2float(yh[p]);
        }
    }

    float2* __restrict__ gp2 = reinterpret_cast<float2*>(gP);
    #pragma unroll
    for (int p = 0; p < NPAIR; p++) {
        int r0 = t + (2 * p)     * RSTRIDE;
        int r1 = t + (2 * p + 1) * RSTRIDE;
        gp2[r0 * PSTRIDE + slice] = make_float2(sA[p], yA[p]);
        gp2[r1 * PSTRIDE + slice] = make_float2(sB[p], yB[p]);
    }
}

// ---------- Kernel C: reduce slices (4 lanes/row) + conv-sigmoid + head-sigmoid ----------
__global__ void __launch_bounds__(256) k_tail(
                       const float* __restrict__ conv_b,
                       const float* __restrict__ head_w, const float* __restrict__ head_b,
                       float* __restrict__ out)
{
    int tid = blockIdx.x * 256 + threadIdx.x;
    int row = tid >> 2;          // 4 lanes per row
    int l   = tid & 3;

    const float4* __restrict__ p = gP + row * (PSTRIDE / 2);
    float sum = 0.f, y = 0.f;
    #pragma unroll
    for (int i = l; i < PSTRIDE / 2; i += 4) {
        float4 v = __ldg(p + i);      // {sum0, y0, sum1, y1}
        sum += v.x + v.z;
        y   += v.y + v.w;
    }
    sum += __shfl_xor_sync(0xffffffffu, sum, 1, 4);
    y   += __shfl_xor_sync(0xffffffffu, y,   1, 4);
    sum += __shfl_xor_sync(0xffffffffu, sum, 2, 4);
    y   += __shfl_xor_sync(0xffffffffu, y,   2, 4);

    if (l == 0) {
        float z = fmaf(y, 1.f / sum, conv_b[0]);
        float f = 1.f / (1.f + expf(-z));
        float logit = fmaf(f, head_w[0], head_b[0]);
        out[row] = 1.f / (1.f + expf(-logit));
    }
}

extern "C" void kernel_launch(void* const* d_in, const int* in_sizes, int n_in,
                              void* d_out, int out_size)
{
    const float* inp  = (const float*)d_in[0];
    const float* Wfm  = (const float*)d_in[1];
    const float* bfm  = (const float*)d_in[2];
    const float* Wc1  = (const float*)d_in[3];
    const float* bc1  = (const float*)d_in[4];
    const float* Wp1  = (const float*)d_in[5];
    const float* bp1  = (const float*)d_in[6];
    const float* Wc2  = (const float*)d_in[7];
    const float* bc2  = (const float*)d_in[8];
    const float* Wp2  = (const float*)d_in[9];
    const float* bp2  = (const float*)d_in[10];
    const float* Wc3  = (const float*)d_in[11];
    const float* bc3  = (const float*)d_in[12];
    const float* rot  = (const float*)d_in[13];
    const float* ent  = (const float*)d_in[14];
    const float* cw   = (const float*)d_in[15];
    const float* cb   = (const float*)d_in[16];
    const float* hw   = (const float*)d_in[17];
    const float* hb   = (const float*)d_in[18];
    float* out = (float*)d_out;

    k_prep<<<NPREPB, 512>>>(inp, Wfm, bfm, Wc1, bc1, Wp1, bp1,
                            Wc2, bc2, Wp2, bp2, Wc3, bc3, rot, ent, cw);
    dim3 gridB(RSTRIDE / 512, NSLICE);   // 4 x 37 = 148 blocks, 16 warps each
    k_attn<<<gridB, 512>>>();
    k_tail<<<NB * 4 / 256, 256>>>(cb, hw, hb, out);
}